// round 9
// baseline (speedup 1.0000x reference)
#include <cuda_runtime.h>
#include <cuda_bf16.h>

// ---------------- problem-size capacities (fixed by the dataset) -------------
#define N_CAP 100000
#define E_CAP 3200000
#define F_IN  512
#define F_MID 16
#define STRIDE 96          // fixed bucket capacity per dst row (deg ~ Poisson(32))
#define NPB   256          // nodes per gemm1 block
#define KCH   32           // k-chunk staged in smem
#define XS_STRIDE 260      // padded node stride: 16B-aligned rows, 2-way STS conflicts

// ---------------- device scratch (accessed ONLY by symbol in device code) ----
__device__ __align__(16) int   g_cnt[N_CAP];            // per-row fill count = degree
__device__ __align__(16) float g_dis[N_CAP];            // (deg+1)^-1/2
__device__ __align__(16) int   g_bkt[N_CAP * STRIDE];   // fixed-stride CSR buckets
__device__ __align__(16) float g_hs1[N_CAP * F_MID];    // dis ⊙ (x @ W1)
__device__ __align__(16) float g_hs2[N_CAP * F_MID];    // dis ⊙ (agg1 @ W2)
__device__ __align__(16) unsigned long long g_wdup[F_IN * F_MID];  // W1, f32x2-duplicated

// packed f32x2 helpers (sm_103a: 2x-rate packed fp32 pipe)
#define FMA_F32X2(d, a, b, c) \
    asm("fma.rn.f32x2 %0, %1, %2, %3;" : "=l"(d) : "l"(a), "l"(b), "l"(c))
#define PACK2(d, f) \
    asm("mov.b64 %0, {%1, %1};" : "=l"(d) : "f"(f))

union F2U { unsigned long long u; float2 f; };

// ---------------- 1: zero counters + build duplicated W1 ---------------------
__global__ void k_zero(const float* __restrict__ w, int N) {
    int i = blockIdx.x * blockDim.x + threadIdx.x;
    if (i < N) g_cnt[i] = 0;
    if (i < F_IN * F_MID) {
        unsigned long long p;
        PACK2(p, w[i]);
        g_wdup[i] = p;
    }
}

// ---------------- 2: bucket fill, 4 edges/thread (no hist, no scan) ----------
__global__ __launch_bounds__(256) void k_fill(const int* __restrict__ ei, int E, int N) {
    int t = blockIdx.x * blockDim.x + threadIdx.x;
    int e4 = t * 4;
    if (e4 + 3 < E) {
        int4 s4 = *(const int4*)(ei + e4);
        int4 d4 = *(const int4*)(ei + E + e4);
        int slot;
        if ((unsigned)d4.x < (unsigned)N && (unsigned)s4.x < (unsigned)N) {
            slot = atomicAdd(&g_cnt[d4.x], 1);
            if (slot < STRIDE) g_bkt[d4.x * STRIDE + slot] = s4.x;
        }
        if ((unsigned)d4.y < (unsigned)N && (unsigned)s4.y < (unsigned)N) {
            slot = atomicAdd(&g_cnt[d4.y], 1);
            if (slot < STRIDE) g_bkt[d4.y * STRIDE + slot] = s4.y;
        }
        if ((unsigned)d4.z < (unsigned)N && (unsigned)s4.z < (unsigned)N) {
            slot = atomicAdd(&g_cnt[d4.z], 1);
            if (slot < STRIDE) g_bkt[d4.z * STRIDE + slot] = s4.z;
        }
        if ((unsigned)d4.w < (unsigned)N && (unsigned)s4.w < (unsigned)N) {
            slot = atomicAdd(&g_cnt[d4.w], 1);
            if (slot < STRIDE) g_bkt[d4.w * STRIDE + slot] = s4.w;
        }
    } else {
        for (int e = e4; e < E; e++) {
            int s = ei[e];
            int d = ei[E + e];
            if ((unsigned)d < (unsigned)N && (unsigned)s < (unsigned)N) {
                int slot = atomicAdd(&g_cnt[d], 1);
                if (slot < STRIDE) g_bkt[d * STRIDE + slot] = s;
            }
        }
    }
}

// ---------------- 3: dis from counts ----------------
__global__ void k_finalize(int N) {
    int i = blockIdx.x * blockDim.x + threadIdx.x;
    if (i < N) g_dis[i] = rsqrtf((float)(g_cnt[i] + 1));   // + self loop
}

// ---------------- 4: GEMM1 (smem-tiled, node-pair packed, W via L2) ----------
// g_hs1 = dis ⊙ (x @ W1).  Block = 256 threads = 256 nodes, 16 chunks of k=32.
// smem = transposed x tile only (33.3 KB -> 6 blocks/SM).
// Thread (ng = t>>2, jg = t&3): nodes 4ng..+4 (2 packed pairs) x features jg*4..+4.
// Per k: 1 LDS.128 x (packed pairs, conflict-free), 2 uniform LDG.128 of
// pre-duplicated W (L2-hot), 8 packed f32x2 FMAs. Zero inner-loop MOVs.
__global__ __launch_bounds__(256) void k_gemm1(const float* __restrict__ x, int N) {
    __shared__ __align__(16) float xs[KCH * XS_STRIDE];   // 33.3 KB

    int t  = threadIdx.x;
    int n0 = blockIdx.x * NPB;
    int r  = t >> 2;     // staging row 0..63
    int c  = t & 3;      // staging col group
    int ng = t >> 2;     // node group (4 nodes)
    int jg = t & 3;      // feature group (4 features)

    // prefetch chunk 0: per thread 8 float4 (4 row-passes x 2 col-quads)
    float4 buf[4][2];
#pragma unroll
    for (int p = 0; p < 4; p++) {
        int n = n0 + p * 64 + r;
        const float* xrow = x + (size_t)n * F_IN;
#pragma unroll
        for (int q = 0; q < 2; q++)
            buf[p][q] = (n < N) ? __ldg((const float4*)(xrow + (c + 4 * q) * 4))
                                : make_float4(0.f, 0.f, 0.f, 0.f);
    }

    unsigned long long acc[2][4];   // [node pair][feature]
#pragma unroll
    for (int P = 0; P < 2; P++)
#pragma unroll
        for (int j = 0; j < 4; j++) acc[P][j] = 0ull;

    for (int chunk = 0; chunk < F_IN / KCH; chunk++) {
        __syncthreads();
        // transposed STS: element (row, kk) -> xs[kk * XS_STRIDE + row]
#pragma unroll
        for (int p = 0; p < 4; p++) {
            int row = p * 64 + r;
#pragma unroll
            for (int q = 0; q < 2; q++) {
                int kk = (c + 4 * q) * 4;
                xs[(kk + 0) * XS_STRIDE + row] = buf[p][q].x;
                xs[(kk + 1) * XS_STRIDE + row] = buf[p][q].y;
                xs[(kk + 2) * XS_STRIDE + row] = buf[p][q].z;
                xs[(kk + 3) * XS_STRIDE + row] = buf[p][q].w;
            }
        }
        __syncthreads();

        // prefetch next chunk (overlaps compute)
        if (chunk + 1 < F_IN / KCH) {
            int k0n = (chunk + 1) * KCH;
#pragma unroll
            for (int p = 0; p < 4; p++) {
                int n = n0 + p * 64 + r;
                const float* xrow = x + (size_t)n * F_IN + k0n;
#pragma unroll
                for (int q = 0; q < 2; q++)
                    buf[p][q] = (n < N) ? __ldg((const float4*)(xrow + (c + 4 * q) * 4))
                                        : make_float4(0.f, 0.f, 0.f, 0.f);
            }
        }

        int k0 = chunk * KCH;
#pragma unroll
        for (int k = 0; k < KCH; k++) {
            // 4 nodes as 2 packed f32x2 pairs (16B aligned: XS_STRIDE*4 % 16 == 0)
            ulonglong2 xv = *(const ulonglong2*)(xs + k * XS_STRIDE + ng * 4);
            // 4 duplicated W values (32B) for features jg*4..+4, uniform L2 load
            const unsigned long long* wrow = g_wdup + (size_t)(k0 + k) * 16 + jg * 4;
            ulonglong2 w01 = __ldg((const ulonglong2*)(wrow));
            ulonglong2 w23 = __ldg((const ulonglong2*)(wrow + 2));
            FMA_F32X2(acc[0][0], xv.x, w01.x, acc[0][0]);
            FMA_F32X2(acc[0][1], xv.x, w01.y, acc[0][1]);
            FMA_F32X2(acc[0][2], xv.x, w23.x, acc[0][2]);
            FMA_F32X2(acc[0][3], xv.x, w23.y, acc[0][3]);
            FMA_F32X2(acc[1][0], xv.y, w01.x, acc[1][0]);
            FMA_F32X2(acc[1][1], xv.y, w01.y, acc[1][1]);
            FMA_F32X2(acc[1][2], xv.y, w23.x, acc[1][2]);
            FMA_F32X2(acc[1][3], xv.y, w23.y, acc[1][3]);
        }
    }

    // epilogue: unpack halves, scale by dis[n], store 16B per (node, j-group)
#pragma unroll
    for (int P = 0; P < 2; P++) {
#pragma unroll
        for (int h = 0; h < 2; h++) {
            int n = n0 + ng * 4 + 2 * P + h;
            if (n < N) {
                float dd = g_dis[n];
                F2U u0, u1, u2, u3;
                u0.u = acc[P][0]; u1.u = acc[P][1]; u2.u = acc[P][2]; u3.u = acc[P][3];
                float4 o;
                o.x = dd * (h ? u0.f.y : u0.f.x);
                o.y = dd * (h ? u1.f.y : u1.f.x);
                o.z = dd * (h ? u2.f.y : u2.f.x);
                o.w = dd * (h ? u3.f.y : u3.f.x);
                *(float4*)(g_hs1 + (size_t)n * 16 + jg * 4) = o;
            }
        }
    }
}

// ---------------- 5/6: aggregation (float4 gather) + fused W2 on layer 0 -----
// warp per dst node; slot sl = lane>>2 (8 edge slots), f = lane&3 (float4 group).
// layer 0: t[d] = dis[d]*(Σ hs1[s] + hs1[d]);  g_hs2[d] = dis[d]*(t[d] @ W2)
// layer 1: out[d] = dis[d]*(Σ hs2[s] + hs2[d])
__global__ __launch_bounds__(256) void k_agg(int layer, const float* __restrict__ w2,
                                             float* __restrict__ out, int N) {
    __shared__ float wt[256];
    if (layer == 0 && threadIdx.x < 256) wt[threadIdx.x] = w2[threadIdx.x];
    if (layer == 0) __syncthreads();

    int warp = (blockIdx.x * blockDim.x + threadIdx.x) >> 5;
    int lane = threadIdx.x & 31;
    if (warp >= N) return;

    const float* hs = (layer == 0) ? g_hs1 : g_hs2;

    int d     = warp;
    int start = d * STRIDE;
    int cnt   = g_cnt[d];
    if (cnt > STRIDE) cnt = STRIDE;
    int sl = lane >> 2;     // edge slot 0..7
    int f  = lane & 3;      // feature group: floats [4f, 4f+4)

    float ax = 0.f, ay = 0.f, az = 0.f, aw = 0.f;

    int base = 0;
    for (; base + 16 <= cnt; base += 16) {
        int sA = __ldg(&g_bkt[start + base + sl]);
        int sB = __ldg(&g_bkt[start + base + 8 + sl]);
        float4 vA = __ldg((const float4*)(hs + (size_t)sA * 16 + f * 4));
        float4 vB = __ldg((const float4*)(hs + (size_t)sB * 16 + f * 4));
        ax += vA.x + vB.x; ay += vA.y + vB.y;
        az += vA.z + vB.z; aw += vA.w + vB.w;
    }
    for (; base < cnt; base += 8) {
        if (base + sl < cnt) {
            int s = __ldg(&g_bkt[start + base + sl]);
            float4 v = __ldg((const float4*)(hs + (size_t)s * 16 + f * 4));
            ax += v.x; ay += v.y; az += v.z; aw += v.w;
        }
    }
#pragma unroll
    for (int off = 4; off < 32; off <<= 1) {
        ax += __shfl_xor_sync(0xffffffffu, ax, off);
        ay += __shfl_xor_sync(0xffffffffu, ay, off);
        az += __shfl_xor_sync(0xffffffffu, az, off);
        aw += __shfl_xor_sync(0xffffffffu, aw, off);
    }

    float4 sv = __ldg((const float4*)(hs + (size_t)d * 16 + f * 4));
    float dd = g_dis[d];
    float tx = dd * (ax + sv.x);
    float ty = dd * (ay + sv.y);
    float tz = dd * (az + sv.z);
    float tw = dd * (aw + sv.w);

    if (layer == 0) {
        float h2 = 0.f;
        int j = lane & 15;
#pragma unroll
        for (int i = 0; i < 16; i++) {
            float cc = ((i & 3) == 0) ? tx : ((i & 3) == 1) ? ty : ((i & 3) == 2) ? tz : tw;
            float ti = __shfl_sync(0xffffffffu, cc, i >> 2);
            h2 += ti * wt[i * 16 + j];
        }
        if (lane < 16) g_hs2[(size_t)d * 16 + j] = dd * h2;
    } else {
        if (sl == 0) {
            float4 o; o.x = tx; o.y = ty; o.z = tz; o.w = tw;
            *((float4*)(out + (size_t)d * 16 + f * 4)) = o;
        }
    }
}

// ---------------- launch ----------------
extern "C" void kernel_launch(void* const* d_in, const int* in_sizes, int n_in,
                              void* d_out, int out_size) {
    const float* x   = (const float*)d_in[0];
    const int*   ei  = (const int*)d_in[1];     // int32 (JAX x64 disabled)
    const float* w1  = (const float*)d_in[2];
    const float* w2  = (const float*)d_in[3];
    float*       out = (float*)d_out;

    int N = in_sizes[0] / F_IN;   // 100000
    int E = in_sizes[1] / 2;      // 3200000
    int E4 = (E + 3) / 4;

    k_zero    <<<(N + 255) / 256, 256>>>(w1, N);          // also builds g_wdup
    k_fill    <<<(E4 + 255) / 256, 256>>>(ei, E, N);
    k_finalize<<<(N + 255) / 256, 256>>>(N);

    k_gemm1<<<(N + NPB - 1) / NPB, 256>>>(x, N);          // profile slot 4
    k_agg<<<(N * 32 + 255) / 256, 256>>>(0, w2, out, N);
    k_agg<<<(N * 32 + 255) / 256, 256>>>(1, w2, out, N);
}

// round 10
// speedup vs baseline: 1.1971x; 1.1971x over previous
#include <cuda_runtime.h>
#include <cuda_bf16.h>

// ---------------- problem-size capacities (fixed by the dataset) -------------
#define N_CAP 100000
#define E_CAP 3200000
#define F_IN  512
#define F_MID 16
#define STRIDE 96          // fixed bucket capacity per dst row (deg ~ Poisson(32))
#define NPB   256          // nodes per gemm1 block
#define KCH   16           // k-chunk staged in smem
#define XSTR  260          // xs node stride: 16B-aligned, 2-way STS conflicts only

// ---------------- device scratch (accessed ONLY by symbol in device code) ----
__device__ __align__(16) int   g_cnt[N_CAP];            // per-row fill count = degree
__device__ __align__(16) float g_dis[N_CAP];            // (deg+1)^-1/2
__device__ __align__(16) int   g_bkt[N_CAP * STRIDE];   // fixed-stride CSR buckets
__device__ __align__(16) float g_hs1[N_CAP * F_MID];    // h1, then dis ⊙ h1 after finscale
__device__ __align__(16) float g_hs2[N_CAP * F_MID];    // dis ⊙ (agg1 @ W2)

// packed f32x2 helpers (sm_103a: 2x-rate packed fp32 pipe)
#define FMA_F32X2(d, a, b, c) \
    asm("fma.rn.f32x2 %0, %1, %2, %3;" : "=l"(d) : "l"(a), "l"(b), "l"(c))
#define PACK2(d, f) \
    asm("mov.b64 %0, {%1, %1};" : "=l"(d) : "f"(f))

// ---------------- 1: zero counters ----------------
__global__ void k_zero(int N) {
    int i = blockIdx.x * blockDim.x + threadIdx.x;
    if (i < N) g_cnt[i] = 0;
}

// ---------------- 2: MERGED kernel: gemm1 blocks + fill blocks ---------------
// blocks [0, g1b)        : h1 = x @ W1 (UNSCALED -> no dependency on fill)
// blocks [g1b, g1b+fillb): bucket fill (atomic slot assignment)
// The two jobs are data-independent; merging overlaps DRAM/FMA-bound GEMM with
// L2-atomic-latency-bound fill in a single capture-safe launch.
__global__ __launch_bounds__(256) void k_main(const float* __restrict__ x,
                                              const float* __restrict__ w,
                                              const int* __restrict__ ei,
                                              int E, int N, int g1b) {
    __shared__ __align__(16) float ws[F_IN * F_MID];   // 32 KB (gemm1 branch only)
    __shared__ __align__(16) float xs[KCH * XSTR];     // 16.6 KB (gemm1 branch only)

    if (blockIdx.x >= g1b) {
        // ---------------- fill branch, 4 edges/thread ----------------
        int t = (blockIdx.x - g1b) * blockDim.x + threadIdx.x;
        int e4 = t * 4;
        if (e4 + 3 < E) {
            int4 s4 = *(const int4*)(ei + e4);
            int4 d4 = *(const int4*)(ei + E + e4);
            int slot;
            if ((unsigned)d4.x < (unsigned)N && (unsigned)s4.x < (unsigned)N) {
                slot = atomicAdd(&g_cnt[d4.x], 1);
                if (slot < STRIDE) g_bkt[d4.x * STRIDE + slot] = s4.x;
            }
            if ((unsigned)d4.y < (unsigned)N && (unsigned)s4.y < (unsigned)N) {
                slot = atomicAdd(&g_cnt[d4.y], 1);
                if (slot < STRIDE) g_bkt[d4.y * STRIDE + slot] = s4.y;
            }
            if ((unsigned)d4.z < (unsigned)N && (unsigned)s4.z < (unsigned)N) {
                slot = atomicAdd(&g_cnt[d4.z], 1);
                if (slot < STRIDE) g_bkt[d4.z * STRIDE + slot] = s4.z;
            }
            if ((unsigned)d4.w < (unsigned)N && (unsigned)s4.w < (unsigned)N) {
                slot = atomicAdd(&g_cnt[d4.w], 1);
                if (slot < STRIDE) g_bkt[d4.w * STRIDE + slot] = s4.w;
            }
        } else {
            for (int e = e4; e < E; e++) {
                int s = ei[e];
                int d = ei[E + e];
                if ((unsigned)d < (unsigned)N && (unsigned)s < (unsigned)N) {
                    int slot = atomicAdd(&g_cnt[d], 1);
                    if (slot < STRIDE) g_bkt[d * STRIDE + slot] = s;
                }
            }
        }
        return;
    }

    // ---------------- gemm1 branch (smem-tiled, R8 layout + stride 260) ------
    int t  = threadIdx.x;
    int n0 = blockIdx.x * NPB;
    int r  = t >> 2;     // staging row 0..63
    int c  = t & 3;      // staging col group
    int ng = t >> 2;     // node group (4 nodes)
    int jg = t & 3;      // feature group (4 features)

    // stage W (read after the first __syncthreads below)
    for (int i = t; i < (F_IN * F_MID) / 4; i += 256)
        ((float4*)ws)[i] = __ldg(&((const float4*)w)[i]);

    // prefetch chunk 0
    float4 buf[4];
#pragma unroll
    for (int p = 0; p < 4; p++) {
        int n = n0 + p * 64 + r;
        buf[p] = (n < N) ? __ldg((const float4*)(x + (size_t)n * F_IN + c * 4))
                         : make_float4(0.f, 0.f, 0.f, 0.f);
    }

    unsigned long long acc[4][2], zero;
    PACK2(zero, 0.0f);
#pragma unroll
    for (int i = 0; i < 4; i++) { acc[i][0] = zero; acc[i][1] = zero; }

    for (int chunk = 0; chunk < F_IN / KCH; chunk++) {
        __syncthreads();
        // transposed STS (2-way conflicts with XSTR=260)
#pragma unroll
        for (int p = 0; p < 4; p++) {
            int row = p * 64 + r;
            xs[(c * 4 + 0) * XSTR + row] = buf[p].x;
            xs[(c * 4 + 1) * XSTR + row] = buf[p].y;
            xs[(c * 4 + 2) * XSTR + row] = buf[p].z;
            xs[(c * 4 + 3) * XSTR + row] = buf[p].w;
        }
        __syncthreads();

        // prefetch next chunk (overlaps compute)
        if (chunk + 1 < F_IN / KCH) {
            int k0n = (chunk + 1) * KCH;
#pragma unroll
            for (int p = 0; p < 4; p++) {
                int n = n0 + p * 64 + r;
                buf[p] = (n < N) ? __ldg((const float4*)(x + (size_t)n * F_IN + k0n + c * 4))
                                 : make_float4(0.f, 0.f, 0.f, 0.f);
            }
        }

        int k0 = chunk * KCH;
#pragma unroll
        for (int k = 0; k < KCH; k++) {
            ulonglong2 wv = *(const ulonglong2*)(ws + (k0 + k) * 16 + jg * 4);
            float4 xv = *(const float4*)(xs + k * XSTR + ng * 4);
            unsigned long long xp0, xp1, xp2, xp3;
            PACK2(xp0, xv.x); PACK2(xp1, xv.y); PACK2(xp2, xv.z); PACK2(xp3, xv.w);
            FMA_F32X2(acc[0][0], xp0, wv.x, acc[0][0]);
            FMA_F32X2(acc[0][1], xp0, wv.y, acc[0][1]);
            FMA_F32X2(acc[1][0], xp1, wv.x, acc[1][0]);
            FMA_F32X2(acc[1][1], xp1, wv.y, acc[1][1]);
            FMA_F32X2(acc[2][0], xp2, wv.x, acc[2][0]);
            FMA_F32X2(acc[2][1], xp2, wv.y, acc[2][1]);
            FMA_F32X2(acc[3][0], xp3, wv.x, acc[3][0]);
            FMA_F32X2(acc[3][1], xp3, wv.y, acc[3][1]);
        }
    }

    // store UNSCALED h1 (dis applied later in k_finscale)
#pragma unroll
    for (int i = 0; i < 4; i++) {
        int n = n0 + ng * 4 + i;
        if (n < N) {
            ulonglong2 v; v.x = acc[i][0]; v.y = acc[i][1];
            *(ulonglong2*)(g_hs1 + (size_t)n * 16 + jg * 4) = v;
        }
    }
}

// ---------------- 3: dis from counts + scale h1 in place --------------------
// 4 threads per node (coalesced float4), lane f==0 writes g_dis.
__global__ void k_finscale(int N) {
    int i = blockIdx.x * blockDim.x + threadIdx.x;
    int node = i >> 2;
    int f    = i & 3;
    if (node >= N) return;
    float dd = rsqrtf((float)(g_cnt[node] + 1));   // + self loop
    if (f == 0) g_dis[node] = dd;
    float4* p = (float4*)(g_hs1 + (size_t)node * 16 + f * 4);
    float4 v = *p;
    v.x *= dd; v.y *= dd; v.z *= dd; v.w *= dd;
    *p = v;
}

// ---------------- 4/5: aggregation (float4 gather) + fused W2 on layer 0 -----
// warp per dst node; slot sl = lane>>2 (8 edge slots), f = lane&3 (float4 group).
// layer 0: t[d] = dis[d]*(Σ hs1[s] + hs1[d]);  g_hs2[d] = dis[d]*(t[d] @ W2)
// layer 1: out[d] = dis[d]*(Σ hs2[s] + hs2[d])
__global__ __launch_bounds__(256) void k_agg(int layer, const float* __restrict__ w2,
                                             float* __restrict__ out, int N) {
    __shared__ float wt[256];
    if (layer == 0 && threadIdx.x < 256) wt[threadIdx.x] = w2[threadIdx.x];
    if (layer == 0) __syncthreads();

    int warp = (blockIdx.x * blockDim.x + threadIdx.x) >> 5;
    int lane = threadIdx.x & 31;
    if (warp >= N) return;

    const float* hs = (layer == 0) ? g_hs1 : g_hs2;

    int d     = warp;
    int start = d * STRIDE;
    int cnt   = g_cnt[d];
    if (cnt > STRIDE) cnt = STRIDE;
    int sl = lane >> 2;     // edge slot 0..7
    int f  = lane & 3;      // feature group: floats [4f, 4f+4)

    float ax = 0.f, ay = 0.f, az = 0.f, aw = 0.f;

    int base = 0;
    for (; base + 16 <= cnt; base += 16) {
        int sA = __ldg(&g_bkt[start + base + sl]);
        int sB = __ldg(&g_bkt[start + base + 8 + sl]);
        float4 vA = __ldg((const float4*)(hs + (size_t)sA * 16 + f * 4));
        float4 vB = __ldg((const float4*)(hs + (size_t)sB * 16 + f * 4));
        ax += vA.x + vB.x; ay += vA.y + vB.y;
        az += vA.z + vB.z; aw += vA.w + vB.w;
    }
    for (; base < cnt; base += 8) {
        if (base + sl < cnt) {
            int s = __ldg(&g_bkt[start + base + sl]);
            float4 v = __ldg((const float4*)(hs + (size_t)s * 16 + f * 4));
            ax += v.x; ay += v.y; az += v.z; aw += v.w;
        }
    }
#pragma unroll
    for (int off = 4; off < 32; off <<= 1) {
        ax += __shfl_xor_sync(0xffffffffu, ax, off);
        ay += __shfl_xor_sync(0xffffffffu, ay, off);
        az += __shfl_xor_sync(0xffffffffu, az, off);
        aw += __shfl_xor_sync(0xffffffffu, aw, off);
    }

    float4 sv = __ldg((const float4*)(hs + (size_t)d * 16 + f * 4));
    float dd = g_dis[d];
    float tx = dd * (ax + sv.x);
    float ty = dd * (ay + sv.y);
    float tz = dd * (az + sv.z);
    float tw = dd * (aw + sv.w);

    if (layer == 0) {
        float h2 = 0.f;
        int j = lane & 15;
#pragma unroll
        for (int i = 0; i < 16; i++) {
            float cc = ((i & 3) == 0) ? tx : ((i & 3) == 1) ? ty : ((i & 3) == 2) ? tz : tw;
            float ti = __shfl_sync(0xffffffffu, cc, i >> 2);
            h2 += ti * wt[i * 16 + j];
        }
        if (lane < 16) g_hs2[(size_t)d * 16 + j] = dd * h2;
    } else {
        if (sl == 0) {
            float4 o; o.x = tx; o.y = ty; o.z = tz; o.w = tw;
            *((float4*)(out + (size_t)d * 16 + f * 4)) = o;
        }
    }
}

// ---------------- launch ----------------
extern "C" void kernel_launch(void* const* d_in, const int* in_sizes, int n_in,
                              void* d_out, int out_size) {
    const float* x   = (const float*)d_in[0];
    const int*   ei  = (const int*)d_in[1];     // int32 (JAX x64 disabled)
    const float* w1  = (const float*)d_in[2];
    const float* w2  = (const float*)d_in[3];
    float*       out = (float*)d_out;

    int N = in_sizes[0] / F_IN;   // 100000
    int E = in_sizes[1] / 2;      // 3200000
    int E4 = (E + 3) / 4;

    int g1b   = (N + NPB - 1) / NPB;        // 391 gemm1 blocks (scheduled first)
    int fillb = (E4 + 255) / 256;           // 3125 fill blocks

    k_zero    <<<(N + 255) / 256, 256>>>(N);
    k_main    <<<g1b + fillb, 256>>>(x, w1, ei, E, N, g1b);   // overlapped fill+gemm1
    k_finscale<<<(N * 4 + 255) / 256, 256>>>(N);

    k_agg<<<(N * 32 + 255) / 256, 256>>>(0, w2, out, N);      // profile slot 4
    k_agg<<<(N * 32 + 255) / 256, 256>>>(1, w2, out, N);
}

// round 11
// speedup vs baseline: 1.4344x; 1.1983x over previous
#include <cuda_runtime.h>
#include <cuda_bf16.h>

// ---------------- problem-size capacities (fixed by the dataset) -------------
#define N_CAP 100000
#define E_CAP 3200000
#define F_IN  512
#define F_MID 16
#define STRIDE 96          // fixed bucket capacity per dst row (deg ~ Poisson(32))
#define NPB   256          // nodes per gemm1 block
#define KCH   16           // k-chunk staged in smem
#define XSTR  260          // xs node stride: 16B-aligned, 2-way STS conflicts only
#define KHALF (F_IN / 2)   // 256 k per split

// ---------------- device scratch (accessed ONLY by symbol in device code) ----
__device__ __align__(16) int   g_cnt[N_CAP];            // per-row fill count = degree
__device__ __align__(16) float g_dis[N_CAP];            // (deg+1)^-1/2
__device__ __align__(16) int   g_bkt[N_CAP * STRIDE];   // fixed-stride CSR buckets
__device__ __align__(16) float g_p0[N_CAP * F_MID];     // split-K partial 0
__device__ __align__(16) float g_p1[N_CAP * F_MID];     // split-K partial 1
__device__ __align__(16) float g_hs1[N_CAP * F_MID];    // dis ⊙ (x @ W1)
__device__ __align__(16) float g_hs2[N_CAP * F_MID];    // dis ⊙ (agg1 @ W2)

// packed f32x2 helpers (sm_103a: 2x-rate packed fp32 pipe)
#define FMA_F32X2(d, a, b, c) \
    asm("fma.rn.f32x2 %0, %1, %2, %3;" : "=l"(d) : "l"(a), "l"(b), "l"(c))
#define PACK2(d, f) \
    asm("mov.b64 %0, {%1, %1};" : "=l"(d) : "f"(f))

// ---------------- 1: zero counters ----------------
__global__ void k_zero(int N) {
    int i = blockIdx.x * blockDim.x + threadIdx.x;
    if (i < N) g_cnt[i] = 0;
}

// ---------------- 2: MERGED kernel: split-K gemm1 blocks + fill blocks -------
// blocks [0, g1b)        : partial h1 = x[:, ksplit] @ W1[ksplit, :] (unscaled)
// blocks [g1b, g1b+fillb): bucket fill (atomic slot assignment)
__global__ __launch_bounds__(256) void k_main(const float* __restrict__ x,
                                              const float* __restrict__ w,
                                              const int* __restrict__ ei,
                                              int E, int N, int g1b) {
    __shared__ __align__(16) float ws[KHALF * F_MID];  // 16 KB (half of W1)
    __shared__ __align__(16) float xs[KCH * XSTR];     // 16.6 KB

    if (blockIdx.x >= g1b) {
        // ---------------- fill branch, 4 edges/thread ----------------
        int t = (blockIdx.x - g1b) * blockDim.x + threadIdx.x;
        int e4 = t * 4;
        if (e4 + 3 < E) {
            int4 s4 = *(const int4*)(ei + e4);
            int4 d4 = *(const int4*)(ei + E + e4);
            int slot;
            if ((unsigned)d4.x < (unsigned)N && (unsigned)s4.x < (unsigned)N) {
                slot = atomicAdd(&g_cnt[d4.x], 1);
                if (slot < STRIDE) g_bkt[d4.x * STRIDE + slot] = s4.x;
            }
            if ((unsigned)d4.y < (unsigned)N && (unsigned)s4.y < (unsigned)N) {
                slot = atomicAdd(&g_cnt[d4.y], 1);
                if (slot < STRIDE) g_bkt[d4.y * STRIDE + slot] = s4.y;
            }
            if ((unsigned)d4.z < (unsigned)N && (unsigned)s4.z < (unsigned)N) {
                slot = atomicAdd(&g_cnt[d4.z], 1);
                if (slot < STRIDE) g_bkt[d4.z * STRIDE + slot] = s4.z;
            }
            if ((unsigned)d4.w < (unsigned)N && (unsigned)s4.w < (unsigned)N) {
                slot = atomicAdd(&g_cnt[d4.w], 1);
                if (slot < STRIDE) g_bkt[d4.w * STRIDE + slot] = s4.w;
            }
        } else {
            for (int e = e4; e < E; e++) {
                int s = ei[e];
                int d = ei[E + e];
                if ((unsigned)d < (unsigned)N && (unsigned)s < (unsigned)N) {
                    int slot = atomicAdd(&g_cnt[d], 1);
                    if (slot < STRIDE) g_bkt[d * STRIDE + slot] = s;
                }
            }
        }
        return;
    }

    // ---------------- split-K gemm1 branch -----------------------------------
    int split = blockIdx.x & 1;               // interleaved co-scheduling
    int nblk  = blockIdx.x >> 1;
    int kbase = split * KHALF;
    float* hp = split ? g_p1 : g_p0;

    int t  = threadIdx.x;
    int n0 = nblk * NPB;
    int r  = t >> 2;     // staging row 0..63
    int c  = t & 3;      // staging col group
    int ng = t >> 2;     // node group (4 nodes)
    int jg = t & 3;      // feature group (4 features)

    // stage this split's half of W (read after first __syncthreads)
    for (int i = t; i < (KHALF * F_MID) / 4; i += 256)
        ((float4*)ws)[i] = __ldg(&((const float4*)(w + kbase * F_MID))[i]);

    // prefetch chunk 0
    float4 buf[4];
#pragma unroll
    for (int p = 0; p < 4; p++) {
        int n = n0 + p * 64 + r;
        buf[p] = (n < N) ? __ldg((const float4*)(x + (size_t)n * F_IN + kbase + c * 4))
                         : make_float4(0.f, 0.f, 0.f, 0.f);
    }

    unsigned long long acc[4][2], zero;
    PACK2(zero, 0.0f);
#pragma unroll
    for (int i = 0; i < 4; i++) { acc[i][0] = zero; acc[i][1] = zero; }

    for (int chunk = 0; chunk < KHALF / KCH; chunk++) {
        __syncthreads();
        // transposed STS (2-way conflicts with XSTR=260)
#pragma unroll
        for (int p = 0; p < 4; p++) {
            int row = p * 64 + r;
            xs[(c * 4 + 0) * XSTR + row] = buf[p].x;
            xs[(c * 4 + 1) * XSTR + row] = buf[p].y;
            xs[(c * 4 + 2) * XSTR + row] = buf[p].z;
            xs[(c * 4 + 3) * XSTR + row] = buf[p].w;
        }
        __syncthreads();

        // prefetch next chunk (overlaps compute)
        if (chunk + 1 < KHALF / KCH) {
            int k0n = kbase + (chunk + 1) * KCH;
#pragma unroll
            for (int p = 0; p < 4; p++) {
                int n = n0 + p * 64 + r;
                buf[p] = (n < N) ? __ldg((const float4*)(x + (size_t)n * F_IN + k0n + c * 4))
                                 : make_float4(0.f, 0.f, 0.f, 0.f);
            }
        }

        int k0 = chunk * KCH;
#pragma unroll
        for (int k = 0; k < KCH; k++) {
            ulonglong2 wv = *(const ulonglong2*)(ws + (k0 + k) * 16 + jg * 4);
            float4 xv = *(const float4*)(xs + k * XSTR + ng * 4);
            unsigned long long xp0, xp1, xp2, xp3;
            PACK2(xp0, xv.x); PACK2(xp1, xv.y); PACK2(xp2, xv.z); PACK2(xp3, xv.w);
            FMA_F32X2(acc[0][0], xp0, wv.x, acc[0][0]);
            FMA_F32X2(acc[0][1], xp0, wv.y, acc[0][1]);
            FMA_F32X2(acc[1][0], xp1, wv.x, acc[1][0]);
            FMA_F32X2(acc[1][1], xp1, wv.y, acc[1][1]);
            FMA_F32X2(acc[2][0], xp2, wv.x, acc[2][0]);
            FMA_F32X2(acc[2][1], xp2, wv.y, acc[2][1]);
            FMA_F32X2(acc[3][0], xp3, wv.x, acc[3][0]);
            FMA_F32X2(acc[3][1], xp3, wv.y, acc[3][1]);
        }
    }

    // store UNSCALED partial (combined + scaled in k_finscale)
#pragma unroll
    for (int i = 0; i < 4; i++) {
        int n = n0 + ng * 4 + i;
        if (n < N) {
            ulonglong2 v; v.x = acc[i][0]; v.y = acc[i][1];
            *(ulonglong2*)(hp + (size_t)n * 16 + jg * 4) = v;
        }
    }
}

// ---------------- 3: combine split-K partials, compute dis, scale -----------
// 4 threads per node (coalesced float4), lane f==0 writes g_dis.
__global__ void k_finscale(int N) {
    int i = blockIdx.x * blockDim.x + threadIdx.x;
    int node = i >> 2;
    int f    = i & 3;
    if (node >= N) return;
    float dd = rsqrtf((float)(g_cnt[node] + 1));   // + self loop
    if (f == 0) g_dis[node] = dd;
    size_t off = (size_t)node * 16 + f * 4;
    float4 a = *(const float4*)(g_p0 + off);
    float4 b = *(const float4*)(g_p1 + off);
    float4 v;
    v.x = dd * (a.x + b.x);
    v.y = dd * (a.y + b.y);
    v.z = dd * (a.z + b.z);
    v.w = dd * (a.w + b.w);
    *(float4*)(g_hs1 + off) = v;
}

// ---------------- 4/5: aggregation (float4 gather) + fused W2 on layer 0 -----
// warp per dst node; slot sl = lane>>2 (8 edge slots), f = lane&3 (float4 group).
// layer 0: t[d] = dis[d]*(Σ hs1[s] + hs1[d]);  g_hs2[d] = dis[d]*(t[d] @ W2)
// layer 1: out[d] = dis[d]*(Σ hs2[s] + hs2[d])
__global__ __launch_bounds__(256) void k_agg(int layer, const float* __restrict__ w2,
                                             float* __restrict__ out, int N) {
    __shared__ float wt[256];
    if (layer == 0 && threadIdx.x < 256) wt[threadIdx.x] = w2[threadIdx.x];
    if (layer == 0) __syncthreads();

    int warp = (blockIdx.x * blockDim.x + threadIdx.x) >> 5;
    int lane = threadIdx.x & 31;
    if (warp >= N) return;

    const float* hs = (layer == 0) ? g_hs1 : g_hs2;

    int d     = warp;
    int start = d * STRIDE;
    int cnt   = g_cnt[d];
    if (cnt > STRIDE) cnt = STRIDE;
    int sl = lane >> 2;     // edge slot 0..7
    int f  = lane & 3;      // feature group: floats [4f, 4f+4)

    float ax = 0.f, ay = 0.f, az = 0.f, aw = 0.f;

    int base = 0;
    for (; base + 16 <= cnt; base += 16) {
        int sA = __ldg(&g_bkt[start + base + sl]);
        int sB = __ldg(&g_bkt[start + base + 8 + sl]);
        float4 vA = __ldg((const float4*)(hs + (size_t)sA * 16 + f * 4));
        float4 vB = __ldg((const float4*)(hs + (size_t)sB * 16 + f * 4));
        ax += vA.x + vB.x; ay += vA.y + vB.y;
        az += vA.z + vB.z; aw += vA.w + vB.w;
    }
    for (; base < cnt; base += 8) {
        if (base + sl < cnt) {
            int s = __ldg(&g_bkt[start + base + sl]);
            float4 v = __ldg((const float4*)(hs + (size_t)s * 16 + f * 4));
            ax += v.x; ay += v.y; az += v.z; aw += v.w;
        }
    }
#pragma unroll
    for (int off = 4; off < 32; off <<= 1) {
        ax += __shfl_xor_sync(0xffffffffu, ax, off);
        ay += __shfl_xor_sync(0xffffffffu, ay, off);
        az += __shfl_xor_sync(0xffffffffu, az, off);
        aw += __shfl_xor_sync(0xffffffffu, aw, off);
    }

    float4 sv = __ldg((const float4*)(hs + (size_t)d * 16 + f * 4));
    float dd = g_dis[d];
    float tx = dd * (ax + sv.x);
    float ty = dd * (ay + sv.y);
    float tz = dd * (az + sv.z);
    float tw = dd * (aw + sv.w);

    if (layer == 0) {
        float h2 = 0.f;
        int j = lane & 15;
#pragma unroll
        for (int i = 0; i < 16; i++) {
            float cc = ((i & 3) == 0) ? tx : ((i & 3) == 1) ? ty : ((i & 3) == 2) ? tz : tw;
            float ti = __shfl_sync(0xffffffffu, cc, i >> 2);
            h2 += ti * wt[i * 16 + j];
        }
        if (lane < 16) g_hs2[(size_t)d * 16 + j] = dd * h2;
    } else {
        if (sl == 0) {
            float4 o; o.x = tx; o.y = ty; o.z = tz; o.w = tw;
            *((float4*)(out + (size_t)d * 16 + f * 4)) = o;
        }
    }
}

// ---------------- launch ----------------
extern "C" void kernel_launch(void* const* d_in, const int* in_sizes, int n_in,
                              void* d_out, int out_size) {
    const float* x   = (const float*)d_in[0];
    const int*   ei  = (const int*)d_in[1];     // int32 (JAX x64 disabled)
    const float* w1  = (const float*)d_in[2];
    const float* w2  = (const float*)d_in[3];
    float*       out = (float*)d_out;

    int N = in_sizes[0] / F_IN;   // 100000
    int E = in_sizes[1] / 2;      // 3200000
    int E4 = (E + 3) / 4;

    int g1b   = 2 * ((N + NPB - 1) / NPB);  // 782 split-K gemm1 blocks
    int fillb = (E4 + 255) / 256;           // 3125 fill blocks

    k_zero    <<<(N + 255) / 256, 256>>>(N);
    k_main    <<<g1b + fillb, 256>>>(x, w1, ei, E, N, g1b);   // overlapped fill+gemm1
    k_finscale<<<(N * 4 + 255) / 256, 256>>>(N);

    k_agg<<<(N * 32 + 255) / 256, 256>>>(0, w2, out, N);
    k_agg<<<(N * 32 + 255) / 256, 256>>>(1, w2, out, N);
}

// round 12
// speedup vs baseline: 1.5323x; 1.0682x over previous
#include <cuda_runtime.h>
#include <cuda_bf16.h>

// ---------------- problem-size capacities (fixed by the dataset) -------------
#define N_CAP 100000
#define E_CAP 3200000
#define F_IN  512
#define F_MID 16
#define STRIDE 96          // fixed bucket capacity per dst row (deg ~ Poisson(32))
#define NPB   256          // nodes per gemm1 block
#define KCH   16           // k-chunk staged in smem
#define XSTR  260          // xs node stride: 16B-aligned, 2-way STS conflicts only
#define KHALF (F_IN / 2)   // 256 k per split

// ---------------- device scratch (accessed ONLY by symbol in device code) ----
__device__ __align__(16) int   g_cnt[N_CAP];            // per-row fill count = degree
__device__ __align__(16) float g_dis[N_CAP];            // (deg+1)^-1/2
__device__ __align__(16) int   g_bkt[N_CAP * STRIDE];   // fixed-stride CSR buckets
__device__ __align__(16) float g_p0[N_CAP * F_MID];     // split-K partial 0
__device__ __align__(16) float g_p1[N_CAP * F_MID];     // split-K partial 1
__device__ __align__(16) float g_hs1[N_CAP * F_MID];    // dis ⊙ (x @ W1)
__device__ __align__(16) float g_hs2[N_CAP * F_MID];    // dis ⊙ (agg1 @ W2)

// packed f32x2 helpers (sm_103a: 2x-rate packed fp32 pipe)
#define FMA_F32X2(d, a, b, c) \
    asm("fma.rn.f32x2 %0, %1, %2, %3;" : "=l"(d) : "l"(a), "l"(b), "l"(c))
#define PACK2(d, f) \
    asm("mov.b64 %0, {%1, %1};" : "=l"(d) : "f"(f))

// ---------------- 1: zero counters ----------------
__global__ void k_zero(int N) {
    int i = blockIdx.x * blockDim.x + threadIdx.x;
    if (i < N) g_cnt[i] = 0;
}

// ---------------- 2: MERGED kernel: split-K gemm1 blocks + fill blocks -------
// blocks [0, g1b)        : partial h1 = x[:, ksplit] @ W1[ksplit, :] (unscaled)
// blocks [g1b, g1b+fillb): bucket fill, 8 edges/thread (atomic slot assignment)
__global__ __launch_bounds__(256) void k_main(const float* __restrict__ x,
                                              const float* __restrict__ w,
                                              const int* __restrict__ ei,
                                              int E, int N, int g1b) {
    __shared__ __align__(16) float ws[KHALF * F_MID];  // 16 KB (half of W1)
    __shared__ __align__(16) float xs[KCH * XSTR];     // 16.6 KB

    if (blockIdx.x >= g1b) {
        // ---------------- fill branch, 8 edges/thread ----------------
        int t = (blockIdx.x - g1b) * blockDim.x + threadIdx.x;
        int e8 = t * 8;
        if (e8 + 7 < E) {
#pragma unroll
            for (int q = 0; q < 2; q++) {
                int4 s4 = *(const int4*)(ei + e8 + q * 4);
                int4 d4 = *(const int4*)(ei + E + e8 + q * 4);
                int slot;
                if ((unsigned)d4.x < (unsigned)N && (unsigned)s4.x < (unsigned)N) {
                    slot = atomicAdd(&g_cnt[d4.x], 1);
                    if (slot < STRIDE) g_bkt[d4.x * STRIDE + slot] = s4.x;
                }
                if ((unsigned)d4.y < (unsigned)N && (unsigned)s4.y < (unsigned)N) {
                    slot = atomicAdd(&g_cnt[d4.y], 1);
                    if (slot < STRIDE) g_bkt[d4.y * STRIDE + slot] = s4.y;
                }
                if ((unsigned)d4.z < (unsigned)N && (unsigned)s4.z < (unsigned)N) {
                    slot = atomicAdd(&g_cnt[d4.z], 1);
                    if (slot < STRIDE) g_bkt[d4.z * STRIDE + slot] = s4.z;
                }
                if ((unsigned)d4.w < (unsigned)N && (unsigned)s4.w < (unsigned)N) {
                    slot = atomicAdd(&g_cnt[d4.w], 1);
                    if (slot < STRIDE) g_bkt[d4.w * STRIDE + slot] = s4.w;
                }
            }
        } else {
            for (int e = e8; e < E; e++) {
                int s = ei[e];
                int d = ei[E + e];
                if ((unsigned)d < (unsigned)N && (unsigned)s < (unsigned)N) {
                    int slot = atomicAdd(&g_cnt[d], 1);
                    if (slot < STRIDE) g_bkt[d * STRIDE + slot] = s;
                }
            }
        }
        return;
    }

    // ---------------- split-K gemm1 branch -----------------------------------
    int split = blockIdx.x & 1;               // interleaved co-scheduling
    int nblk  = blockIdx.x >> 1;
    int kbase = split * KHALF;
    float* hp = split ? g_p1 : g_p0;

    int t  = threadIdx.x;
    int n0 = nblk * NPB;
    int r  = t >> 2;     // staging row 0..63
    int c  = t & 3;      // staging col group
    int ng = t >> 2;     // node group (4 nodes)
    int jg = t & 3;      // feature group (4 features)

    // stage this split's half of W (read after first __syncthreads)
    for (int i = t; i < (KHALF * F_MID) / 4; i += 256)
        ((float4*)ws)[i] = __ldg(&((const float4*)(w + kbase * F_MID))[i]);

    // prefetch chunk 0
    float4 buf[4];
#pragma unroll
    for (int p = 0; p < 4; p++) {
        int n = n0 + p * 64 + r;
        buf[p] = (n < N) ? __ldg((const float4*)(x + (size_t)n * F_IN + kbase + c * 4))
                         : make_float4(0.f, 0.f, 0.f, 0.f);
    }

    unsigned long long acc[4][2], zero;
    PACK2(zero, 0.0f);
#pragma unroll
    for (int i = 0; i < 4; i++) { acc[i][0] = zero; acc[i][1] = zero; }

    for (int chunk = 0; chunk < KHALF / KCH; chunk++) {
        __syncthreads();
        // transposed STS (2-way conflicts with XSTR=260)
#pragma unroll
        for (int p = 0; p < 4; p++) {
            int row = p * 64 + r;
            xs[(c * 4 + 0) * XSTR + row] = buf[p].x;
            xs[(c * 4 + 1) * XSTR + row] = buf[p].y;
            xs[(c * 4 + 2) * XSTR + row] = buf[p].z;
            xs[(c * 4 + 3) * XSTR + row] = buf[p].w;
        }
        __syncthreads();

        // prefetch next chunk (overlaps compute)
        if (chunk + 1 < KHALF / KCH) {
            int k0n = kbase + (chunk + 1) * KCH;
#pragma unroll
            for (int p = 0; p < 4; p++) {
                int n = n0 + p * 64 + r;
                buf[p] = (n < N) ? __ldg((const float4*)(x + (size_t)n * F_IN + k0n + c * 4))
                                 : make_float4(0.f, 0.f, 0.f, 0.f);
            }
        }

        int k0 = chunk * KCH;
#pragma unroll
        for (int k = 0; k < KCH; k++) {
            ulonglong2 wv = *(const ulonglong2*)(ws + (k0 + k) * 16 + jg * 4);
            float4 xv = *(const float4*)(xs + k * XSTR + ng * 4);
            unsigned long long xp0, xp1, xp2, xp3;
            PACK2(xp0, xv.x); PACK2(xp1, xv.y); PACK2(xp2, xv.z); PACK2(xp3, xv.w);
            FMA_F32X2(acc[0][0], xp0, wv.x, acc[0][0]);
            FMA_F32X2(acc[0][1], xp0, wv.y, acc[0][1]);
            FMA_F32X2(acc[1][0], xp1, wv.x, acc[1][0]);
            FMA_F32X2(acc[1][1], xp1, wv.y, acc[1][1]);
            FMA_F32X2(acc[2][0], xp2, wv.x, acc[2][0]);
            FMA_F32X2(acc[2][1], xp2, wv.y, acc[2][1]);
            FMA_F32X2(acc[3][0], xp3, wv.x, acc[3][0]);
            FMA_F32X2(acc[3][1], xp3, wv.y, acc[3][1]);
        }
    }

    // store UNSCALED partial (combined + scaled in k_finscale)
#pragma unroll
    for (int i = 0; i < 4; i++) {
        int n = n0 + ng * 4 + i;
        if (n < N) {
            ulonglong2 v; v.x = acc[i][0]; v.y = acc[i][1];
            *(ulonglong2*)(hp + (size_t)n * 16 + jg * 4) = v;
        }
    }
}

// ---------------- 3: combine split-K partials, compute dis, scale -----------
__global__ void k_finscale(int N) {
    int i = blockIdx.x * blockDim.x + threadIdx.x;
    int node = i >> 2;
    int f    = i & 3;
    if (node >= N) return;
    float dd = rsqrtf((float)(g_cnt[node] + 1));   // + self loop
    if (f == 0) g_dis[node] = dd;
    size_t off = (size_t)node * 16 + f * 4;
    float4 a = *(const float4*)(g_p0 + off);
    float4 b = *(const float4*)(g_p1 + off);
    float4 v;
    v.x = dd * (a.x + b.x);
    v.y = dd * (a.y + b.y);
    v.z = dd * (a.z + b.z);
    v.w = dd * (a.w + b.w);
    *(float4*)(g_hs1 + off) = v;
}

// ---------------- 4/5: aggregation, 2 dst nodes per warp --------------------
// halfwarp h = lane>>4 owns node d = warp*2+h; within 16 lanes:
// sl = (lane>>2)&3 (4 edge slots), f = lane&3 (float4 feature group).
// layer 0: t[d] = dis[d]*(Σ hs1[s] + hs1[d]);  g_hs2[d] = dis[d]*(t[d] @ W2)
// layer 1: out[d] = dis[d]*(Σ hs2[s] + hs2[d])
__global__ __launch_bounds__(256) void k_agg(int layer, const float* __restrict__ w2,
                                             float* __restrict__ out, int N) {
    __shared__ float wt[256];
    if (layer == 0 && threadIdx.x < 256) wt[threadIdx.x] = w2[threadIdx.x];
    if (layer == 0) __syncthreads();

    int warp = (blockIdx.x * blockDim.x + threadIdx.x) >> 5;
    int lane = threadIdx.x & 31;
    int half = lane >> 4;
    int d    = warp * 2 + half;
    if (d >= N) return;

    const float* hs = (layer == 0) ? g_hs1 : g_hs2;

    int start = d * STRIDE;
    int cnt   = g_cnt[d];
    if (cnt > STRIDE) cnt = STRIDE;
    int sl = (lane >> 2) & 3;   // edge slot 0..3 within halfwarp
    int f  = lane & 3;          // feature group: floats [4f, 4f+4)

    float ax = 0.f, ay = 0.f, az = 0.f, aw = 0.f;

    int base = 0;
    // 8 edges per iteration per node: 2 independent L2 chains per lane
    for (; base + 8 <= cnt; base += 8) {
        int sA = __ldg(&g_bkt[start + base + sl]);
        int sB = __ldg(&g_bkt[start + base + 4 + sl]);
        float4 vA = __ldg((const float4*)(hs + (size_t)sA * 16 + f * 4));
        float4 vB = __ldg((const float4*)(hs + (size_t)sB * 16 + f * 4));
        ax += vA.x + vB.x; ay += vA.y + vB.y;
        az += vA.z + vB.z; aw += vA.w + vB.w;
    }
    for (; base < cnt; base += 4) {
        if (base + sl < cnt) {
            int s = __ldg(&g_bkt[start + base + sl]);
            float4 v = __ldg((const float4*)(hs + (size_t)s * 16 + f * 4));
            ax += v.x; ay += v.y; az += v.z; aw += v.w;
        }
    }
    // reduce across the 4 slots (xor 4, 8 stays within the 16-lane half)
#pragma unroll
    for (int off = 4; off <= 8; off <<= 1) {
        ax += __shfl_xor_sync(0xffffffffu, ax, off);
        ay += __shfl_xor_sync(0xffffffffu, ay, off);
        az += __shfl_xor_sync(0xffffffffu, az, off);
        aw += __shfl_xor_sync(0xffffffffu, aw, off);
    }

    // self loop (pre-scaled), then scale by dis[d]
    float4 sv = __ldg((const float4*)(hs + (size_t)d * 16 + f * 4));
    float dd = g_dis[d];
    float tx = dd * (ax + sv.x);
    float ty = dd * (ay + sv.y);
    float tz = dd * (az + sv.z);
    float tw = dd * (aw + sv.w);

    if (layer == 0) {
        // fused GEMM2: feature i of this node lives in component i&3 of
        // absolute lane (half<<4) + (i>>2). Each of the 16 lanes computes j.
        int j = lane & 15;
        int lb = half << 4;
        float h2 = 0.f;
#pragma unroll
        for (int i = 0; i < 16; i++) {
            float cc = ((i & 3) == 0) ? tx : ((i & 3) == 1) ? ty : ((i & 3) == 2) ? tz : tw;
            float ti = __shfl_sync(0xffffffffu, cc, lb + (i >> 2));
            h2 += ti * wt[i * 16 + j];
        }
        g_hs2[(size_t)d * 16 + j] = dd * h2;   // all 32 lanes: 128B per warp
    } else {
        if (sl == 0) {   // lanes {0..3} and {16..19} store float4 rows
            float4 o; o.x = tx; o.y = ty; o.z = tz; o.w = tw;
            *((float4*)(out + (size_t)d * 16 + f * 4)) = o;
        }
    }
}

// ---------------- launch ----------------
extern "C" void kernel_launch(void* const* d_in, const int* in_sizes, int n_in,
                              void* d_out, int out_size) {
    const float* x   = (const float*)d_in[0];
    const int*   ei  = (const int*)d_in[1];     // int32 (JAX x64 disabled)
    const float* w1  = (const float*)d_in[2];
    const float* w2  = (const float*)d_in[3];
    float*       out = (float*)d_out;

    int N = in_sizes[0] / F_IN;   // 100000
    int E = in_sizes[1] / 2;      // 3200000
    int E8 = (E + 7) / 8;

    int g1b   = 2 * ((N + NPB - 1) / NPB);  // 782 split-K gemm1 blocks
    int fillb = (E8 + 255) / 256;           // 1563 fill blocks

    k_zero    <<<(N + 255) / 256, 256>>>(N);
    k_main    <<<g1b + fillb, 256>>>(x, w1, ei, E, N, g1b);   // overlapped fill+gemm1
    k_finscale<<<(N * 4 + 255) / 256, 256>>>(N);

    int aggw = (N + 1) / 2;                  // warps (2 nodes each)
    k_agg<<<(aggw * 32 + 255) / 256, 256>>>(0, w2, out, N);
    k_agg<<<(aggw * 32 + 255) / 256, 256>>>(1, w2, out, N);
}